// round 16
// baseline (speedup 1.0000x reference)
#include <cuda_runtime.h>
#include <cstdint>

// Problem constants (from reference)
#define NTOKENS    8192
#define TOPK       2
#define HIDDEN     4096
#define NUM_GROUPS 2
#define M_FULL     (NTOKENS * TOPK)   // 16384

#define ROW_F4      (HIDDEN / 4)               // 1024 float4 per row
#define CHUNK_F4    32                         // float4 per 512B chunk
#define NCHUNK      (ROW_F4 / CHUNK_F4)        // 32 chunks
#define TOK_PER_CTA 8                          // 8 warps -> 8 tokens per CTA

// ---------------------------------------------------------------------------
// Single fused persistent-style kernel:
//   out[t,:] = buf[0,i0,:] + buf[0,i1,:] + buf[1,i0,:] + buf[1,i1,:]
//
//   grid = (NTOKENS/8) = 1024 CTAs, block = 256 (8 warps). One warp owns one
//   token and loops over all 32 x 512B column chunks internally (2 chunks per
//   unrolled iteration -> 8 independent LDG.128 in flight).
//
//   L2 slab coherence by CO-RESIDENCY: the grid is ~one resident wave, and
//   every warp sweeps chunks in the same order, so at any instant the live
//   read working set is ~2 groups x 16384 rows x (512B x small skew) =
//   16-48MB -> L2-resident; duplicate-index rows hit L2 (read traffic at the
//   ~324MB dedup floor, as measured in R12-R15). __stcs keeps the 128MB
//   write stream from evicting the slab.
//
//   vs R12-R15: index fetch + dtype detection execute ONCE per token instead
//   of once per (token, chunk) — removes 32x redundant prologue work (alu%
//   and issue% overhead) from the HBM-bound inner loop.
//
//   Index dtype detection (per warp): odd int32 words of the index buffer are
//   all-zero iff dtype is int64 (values < 16384). All lanes read the same
//   128B (L1 broadcast), REDUX.OR decides. Reads valid for either dtype
//   (int32 buffer is exactly 128KB). P(misdetect) = 2^-448.
// ---------------------------------------------------------------------------
__global__ __launch_bounds__(256) void k_gather_sum(
    const float* __restrict__ buf,
    const void*  __restrict__ idx,
    float*       __restrict__ out)
{
    const int warp = threadIdx.x >> 5;
    const int lane = threadIdx.x & 31;
    const int t    = blockIdx.x * TOK_PER_CTA + warp;

    // ---- once-per-token prologue ----
    const int probe = __ldg(&((const int*)idx)[2 * lane + 1]);
    const bool is64 = (__reduce_or_sync(0xFFFFFFFFu, probe) == 0);

    int i0, i1;
    if (is64) {
        const longlong2 ll = __ldg(&((const longlong2*)idx)[t]);
        i0 = (int)ll.x;  i1 = (int)ll.y;
    } else {
        const int2 ii = __ldg(&((const int2*)idx)[t]);
        i0 = ii.x;  i1 = ii.y;
    }

    const float4* __restrict__ b4 = (const float4*)buf;
    const float4* p00 = b4 + (size_t)i0 * ROW_F4 + lane;              // g0, i0
    const float4* p01 = b4 + (size_t)i1 * ROW_F4 + lane;              // g0, i1
    const float4* p10 = b4 + ((size_t)M_FULL + i0) * ROW_F4 + lane;   // g1, i0
    const float4* p11 = b4 + ((size_t)M_FULL + i1) * ROW_F4 + lane;   // g1, i1
    float4* __restrict__ o4 = (float4*)out + (size_t)t * ROW_F4 + lane;

    // ---- chunk sweep: 16 iterations x 2 chunks (8 LDG.128 in flight) ----
    #pragma unroll
    for (int c = 0; c < NCHUNK; c += 2) {
        const int ca = c * CHUNK_F4;
        const int cb = ca + CHUNK_F4;

        const float4 a0 = __ldg(p00 + ca);
        const float4 a1 = __ldg(p01 + ca);
        const float4 a2 = __ldg(p10 + ca);
        const float4 a3 = __ldg(p11 + ca);
        const float4 b0 = __ldg(p00 + cb);
        const float4 b1 = __ldg(p01 + cb);
        const float4 b2 = __ldg(p10 + cb);
        const float4 b3 = __ldg(p11 + cb);

        float4 sa, sb;
        sa.x = (a0.x + a1.x) + (a2.x + a3.x);
        sa.y = (a0.y + a1.y) + (a2.y + a3.y);
        sa.z = (a0.z + a1.z) + (a2.z + a3.z);
        sa.w = (a0.w + a1.w) + (a2.w + a3.w);
        sb.x = (b0.x + b1.x) + (b2.x + b3.x);
        sb.y = (b0.y + b1.y) + (b2.y + b3.y);
        sb.z = (b0.z + b1.z) + (b2.z + b3.z);
        sb.w = (b0.w + b1.w) + (b2.w + b3.w);

        __stcs(o4 + ca, sa);
        __stcs(o4 + cb, sb);
    }
}

// ---------------------------------------------------------------------------
// Launch contract
//   d_in[0]: gemm_buffer   float32 [NUM_GROUPS, M_FULL, HIDDEN]
//   d_in[1]: scatter_index int32 or int64 [NTOKENS, TOPK] (device-detected)
//   d_out  : float32 [NTOKENS, HIDDEN]
// ---------------------------------------------------------------------------
extern "C" void kernel_launch(void* const* d_in, const int* in_sizes, int n_in,
                              void* d_out, int out_size) {
    const float* buf = (const float*)d_in[0];
    const void*  idx = d_in[1];
    float*       out = (float*)d_out;

    k_gather_sum<<<NTOKENS / TOK_PER_CTA, 256>>>(buf, idx, out);
}

// round 17
// speedup vs baseline: 1.1830x; 1.1830x over previous
#include <cuda_runtime.h>
#include <cstdint>

// Problem constants (from reference)
#define NTOKENS    8192
#define TOPK       2
#define HIDDEN     4096
#define NUM_GROUPS 2
#define M_FULL     (NTOKENS * TOPK)   // 16384

#define CHUNK_F4    32                         // float4 per chunk = 512 B
#define ROW_F4      (HIDDEN / 4)               // 1024 float4 per row
#define NCHUNK      (ROW_F4 / CHUNK_F4)        // 32 chunks
#define TOK_PER_CTA 8                          // 8 warps -> 8 tokens per CTA

// ---------------------------------------------------------------------------
// Single fused kernel: out[t,:] = buf[0,i0,:]+buf[0,i1,:]+buf[1,i0,:]+buf[1,i1,:]
//
//   grid = (NTOKENS/8, NCHUNK), block = 256 (8 warps).
//   Warp w of block (x, c) handles token t = x*8+w, 512B column chunk c.
//   Grid-ordered slab scheduling (grid.y = chunk, x fastest) is load-bearing:
//   it keeps the per-chunk source slice (2 groups x 16384 rows x 512B = 16MB,
//   ~10.4MB distinct) L2-resident so duplicate-index rows hit L2 — measured
//   at the ~449MB dedup floor in R12-R15. (R16 falsified the persistent
//   co-residency variant: warps drift, traffic 485MB, BW 5.6TB/s.)
//
//   Index dtype detection (per warp, branchless): odd int32 words of the
//   index buffer are all-zero iff dtype is int64 (values < 16384). All lanes
//   read the same 128B (L1 broadcast); REDUX.OR decides; SELs pick between
//   the two pre-loaded dtype views. All reads in-bounds for either dtype
//   (int32 buffer is exactly 128KB). P(misdetect) = 2^-448.
//
//   R17 delta (single variable vs R13): output stores use __stwt
//   (write-through) instead of __stcs. Fully-written coalesced 512B warp
//   stores go straight to DRAM without ever sitting dirty in L2 — removes
//   dirty-eviction bursts from the DRAM read/write turnaround and leaves
//   strictly more L2 for the read slab.
// ---------------------------------------------------------------------------
__global__ __launch_bounds__(256) void k_gather_sum(
    const float* __restrict__ buf,
    const void*  __restrict__ idx,
    float*       __restrict__ out)
{
    const int warp = threadIdx.x >> 5;
    const int lane = threadIdx.x & 31;
    const int t    = blockIdx.x * TOK_PER_CTA + warp;
    const int c    = blockIdx.y;

    // --- issue all three index-path loads independently (no branch) ---
    const int       probe = __ldg(&((const int*)idx)[2 * lane + 1]);
    const longlong2 ll    = __ldg(&((const longlong2*)idx)[t]);   // int64 view
    const int2      ii    = __ldg(&((const int2*)idx)[t]);        // int32 view

    const bool is64 = (__reduce_or_sync(0xFFFFFFFFu, probe) == 0);
    const int i0 = is64 ? (int)ll.x : ii.x;
    const int i1 = is64 ? (int)ll.y : ii.y;

    const float4* __restrict__ b4 = (const float4*)buf;
    const int col = c * CHUNK_F4 + lane;

    const size_t r00 = (size_t)i0 * ROW_F4 + col;              // g0, i0
    const size_t r01 = (size_t)i1 * ROW_F4 + col;              // g0, i1
    const size_t r10 = ((size_t)M_FULL + i0) * ROW_F4 + col;   // g1, i0
    const size_t r11 = ((size_t)M_FULL + i1) * ROW_F4 + col;   // g1, i1

    // 4 independent LDG.128 in flight
    const float4 a = __ldg(&b4[r00]);
    const float4 b = __ldg(&b4[r01]);
    const float4 d = __ldg(&b4[r10]);
    const float4 e = __ldg(&b4[r11]);

    float4 s;
    s.x = (a.x + b.x) + (d.x + e.x);
    s.y = (a.y + b.y) + (d.y + e.y);
    s.z = (a.z + b.z) + (d.z + e.z);
    s.w = (a.w + b.w) + (d.w + e.w);

    __stwt((float4*)out + (size_t)t * ROW_F4 + col, s);
}

// ---------------------------------------------------------------------------
// Launch contract
//   d_in[0]: gemm_buffer   float32 [NUM_GROUPS, M_FULL, HIDDEN]
//   d_in[1]: scatter_index int32 or int64 [NTOKENS, TOPK] (device-detected)
//   d_out  : float32 [NTOKENS, HIDDEN]
// ---------------------------------------------------------------------------
extern "C" void kernel_launch(void* const* d_in, const int* in_sizes, int n_in,
                              void* d_out, int out_size) {
    const float* buf = (const float*)d_in[0];
    const void*  idx = d_in[1];
    float*       out = (float*)d_out;

    dim3 grid(NTOKENS / TOK_PER_CTA, NCHUNK);   // (1024, 32)
    k_gather_sum<<<grid, 256>>>(buf, idx, out);
}